// round 16
// baseline (speedup 1.0000x reference)
#include <cuda_runtime.h>

// ---------------- Problem constants ----------------
#define NBOX 8000          // 5 anchors * 40 * 40
#define HW 40
#define NCLS 20
#define CHSTRIDE (HW*HW)   // 1600 floats between channels
#define STRIDEPX 8.0f      // 320 / 40

#define JC 16
#define CHUNKMAX 500       // ceil(8000/16)
#define IGROUPS 32         // 32*256 = 8192 >= NV

#define MMASK 256          // mask-matrix fast-path capacity (expected M ~ 200)
#define NW 8               // 256/32
#define CAP2 1024          // per-class precomputed-slot capacity (mid path)
#define NMST 1024          // k_nms threads

// ---------------- Scratch (device globals, no allocation) ----------------
// key layout: [63:32]=~bits(conf), [31:5]=idx, [4:0]=cls.  cls<32 => low-word order == idx order.
__device__ float              d_dec6[NBOX * 6];      // decoded rows, original index order
__device__ unsigned long long d_vkey[NBOX];          // valid keys (packed)
__device__ int                d_nv;                  // valid count accumulator
__device__ unsigned           d_partial[JC * NBOX];  // packed: rank | cls_rank<<16
__device__ int                d_gcnt[IGROUPS];       // per-i-group chunk completion counters
__device__ int                d_cnt[NCLS];           // per-class candidate count
__device__ float4             d_cg4 [NCLS * CAP2];   // slot (cls,rc): x1,y1,x2,y2
__device__ float              d_car [NCLS * CAP2];   // slot: area
__device__ int                d_cr  [NCLS * CAP2];   // slot: output row (global rank)
__device__ float              d_crow6[NCLS * CAP2 * 6]; // slot: full output row
__device__ int                d_cand[NCLS * NBOX];   // fallback only: r | orig<<16

// ---------------- K1: decode + valid append + zero output/counters ----------------
__global__ void k_decode(const float* __restrict__ x, const float* __restrict__ anchors,
                         float* __restrict__ out) {
    int tid = threadIdx.x;
    int gid = blockIdx.x * 128 + tid;
    int nthr = gridDim.x * 128;

    // zero output (poisoned before timing) and counters
    for (int k = gid; k < NBOX * 6; k += nthr) out[k] = 0.0f;
    if (gid < NCLS)   d_cnt[gid] = 0;
    if (gid < IGROUPS) d_gcnt[gid] = 0;

    int  i   = gid;
    bool inb = (i < NBOX);
    int  ii  = inb ? i : 0;    // clamp for safe loads

    int a   = ii / (HW * HW);
    int rem = ii - a * (HW * HW);
    int gy  = rem / HW;
    int gx  = rem - gy * HW;
    int base = ((a * 25) * HW + gy) * HW + gx;

    // hoist all 25 loads (max MLP)
    float t[5];
#pragma unroll
    for (int k = 0; k < 5; k++) t[k] = x[base + k * CHSTRIDE];
    float cl[NCLS];
#pragma unroll
    for (int c = 0; c < NCLS; c++) cl[c] = x[base + (5 + c) * CHSTRIDE];

    float tx   = 1.0f / (1.0f + expf(-t[0]));
    float ty   = 1.0f / (1.0f + expf(-t[1]));
    float conf = 1.0f / (1.0f + expf(-t[4]));

    float aw = anchors[a * 2 + 0];
    float ah = anchors[a * 2 + 1];

    float bx = (tx + (float)gx) * STRIDEPX;
    float by = (ty + (float)gy) * STRIDEPX;
    float bw = expf(t[2]) * aw * STRIDEPX;
    float bh = expf(t[3]) * ah * STRIDEPX;

    // argmax (strict '>' keeps first occurrence like jnp.argmax)
    float best = cl[0];
    int bc = 0;
#pragma unroll
    for (int c = 1; c < NCLS; c++)
        if (cl[c] > best) { best = cl[c]; bc = c; }

    if (!inb) return;

    d_dec6[i * 6 + 0] = bx;
    d_dec6[i * 6 + 1] = by;
    d_dec6[i * 6 + 2] = bw;
    d_dec6[i * 6 + 3] = bh;
    d_dec6[i * 6 + 4] = conf;
    d_dec6[i * 6 + 5] = (float)bc;

    // valid (conf > 0.5 <=> logit > 0): contiguous append.
    // Slot order nondeterministic; ranks are value-based -> deterministic output.
    if (t[4] > 0.0f) {
        int slot = atomicAdd(&d_nv, 1);
        unsigned u = __float_as_uint(conf);     // conf in (0,1): bits monotone
        d_vkey[slot] = ((unsigned long long)(~u) << 32)
                     | (unsigned long long)(((unsigned)i << 5) | (unsigned)bc);
    }
}

// ---------------- K2: chunked rank + last-arriver scatter (fused) ----------------
__global__ void k_rank() {
    __shared__ unsigned long long sk[CHUNKMAX];
    __shared__ int slast;
    int NV = d_nv;
    int CS = (NV + JC - 1) / JC;
    int b  = blockIdx.x;
    int g  = b / JC;                 // i-group 0..31
    int cch = b - g * JC;            // chunk 0..15
    int j0 = cch * CS;
    int cnt = NV - j0; if (cnt > CS) cnt = CS; if (cnt < 0) cnt = 0;
    for (int t = threadIdx.x; t < cnt; t += 256)
        sk[t] = d_vkey[j0 + t];
    __syncthreads();
    int i = g * 256 + threadIdx.x;
    if (i < NV) {
        unsigned long long my = d_vkey[i];
        unsigned acc = 0;
#pragma unroll 8
        for (int j = 0; j < cnt; j++) {
            unsigned long long kj = sk[j];
            bool lt = kj < my;
            bool sm = (((unsigned)kj ^ (unsigned)my) & 31u) == 0u;   // same class
            acc += lt ? (1u + ((sm ? 1u : 0u) << 16)) : 0u;
        }
        d_partial[cch * NBOX + i] = acc;
    }
    // completion: last of the 16 chunk-blocks for group g performs the scatter
    __syncthreads();
    if (threadIdx.x == 0) {
        __threadfence();
        slast = (atomicAdd(&d_gcnt[g], 1) == JC - 1) ? 1 : 0;
    }
    __syncthreads();
    if (!slast) return;
    __threadfence();   // acquire: prior blocks' partials visible (release via their fence+atomic)

    if (i < NV) {
        unsigned s = 0;
#pragma unroll
        for (int c = 0; c < JC; c++) s += d_partial[c * NBOX + i];
        int r  = (int)(s & 0xffffu);   // global rank among valid == output row
        int rc = (int)(s >> 16);       // class rank (unique within class)
        unsigned long long key = d_vkey[i];
        unsigned lowk = (unsigned)key;
        int orig = (int)(lowk >> 5);
        int cls  = (int)(lowk & 31u);
        atomicAdd(&d_cnt[cls], 1);
        d_cand[cls * NBOX + rc] = r | (orig << 16);  // fallback path
        if (rc < CAP2) {
            float cx = d_dec6[orig * 6 + 0];
            float cy = d_dec6[orig * 6 + 1];
            float w  = d_dec6[orig * 6 + 2];
            float h  = d_dec6[orig * 6 + 3];
            float x1 = cx - 0.5f * w, y1 = cy - 0.5f * h;
            float x2 = cx + 0.5f * w, y2 = cy + 0.5f * h;
            int slot = cls * CAP2 + rc;
            d_cg4[slot] = make_float4(x1, y1, x2, y2);
            d_car[slot] = fabsf((x2 - x1) * (y2 - y1));
            d_cr [slot] = r;
            d_crow6[slot * 6 + 0] = cx;
            d_crow6[slot * 6 + 1] = cy;
            d_crow6[slot * 6 + 2] = w;
            d_crow6[slot * 6 + 3] = h;
            d_crow6[slot * 6 + 4] = d_dec6[orig * 6 + 4];
            d_crow6[slot * 6 + 5] = d_dec6[orig * 6 + 5];
        }
    }
}

// IoU >= 0.5 <=> 2*inter >= union (division-free)
__device__ __forceinline__ bool sup_test4(float4 bi, float ai, float4 bj, float aj) {
    float iw = fmaxf(fminf(bi.z, bj.z) - fmaxf(bi.x, bj.x), 0.0f);
    float ih = fmaxf(fminf(bi.w, bj.w) - fmaxf(bi.y, bj.y), 0.0f);
    float inter = iw * ih;
    float denom = ai + aj - inter + 1e-6f;
    return 2.0f * inter >= denom;
}

// ---------------- K3: per-class NMS (pure: load -> fill -> sweep -> emit) ----------------
__global__ __launch_bounds__(NMST, 1)
void k_nms(float* __restrict__ out) {
    __shared__ float4   sb4[CAP2];              // x1,y1,x2,y2 per slot
    __shared__ float    sar[CAP2];
    __shared__ int      sr[CAP2];
    __shared__ unsigned smask[MMASK * NW];
    __shared__ unsigned srow[NW], skw[NW];

    int c    = blockIdx.x;
    int tid  = threadIdx.x;
    int lane = tid & 31;
    int warp = tid >> 5;

    if (c == 0 && tid == 0) d_nv = 0;   // reset accumulator for next graph replay
    if (tid < NW) srow[tid] = 0;

    int M = d_cnt[c];
    if (M == 0) return;

    if (M <= CAP2) {
        // ---- coalesced load of precomputed per-class slots ----
        for (int t = tid; t < M; t += NMST) {
            sb4[t] = d_cg4[c * CAP2 + t];
            sar[t] = d_car[c * CAP2 + t];
            sr [t] = d_cr [c * CAP2 + t];
        }
        __syncthreads();

        if (M <= MMASK) {
            // ---- ballot mask fill: one warp per row, 32 warps ----
            int nw = (M + 31) >> 5;
            for (int i = warp; i < M; i += 32) {
                float4 bi = sb4[i];
                float  ai = sar[i];
                int wq0 = (i + 1) >> 5;
                unsigned rowany = 0;
                if (lane == 0)
                    for (int q = 0; q < wq0; q++) smask[i * NW + q] = 0;
                for (int wq = wq0; wq < nw; wq++) {
                    int j = (wq << 5) + lane;
                    bool s = (j > i) && (j < M) && sup_test4(bi, ai, sb4[j], sar[j]);
                    unsigned bits = __ballot_sync(0xffffffffu, s);
                    if (lane == 0) smask[i * NW + wq] = bits;
                    rowany |= bits;
                }
                if (lane == 0 && rowany) atomicOr(&srow[i >> 5], 1u << (i & 31));
            }
            __syncthreads();

            // ---- two-level sweep (warp 0): intra-word serial chain, cross-word parallel ----
            if (tid < 32) {
                unsigned kwq = 0;                      // lane q holds keep-word q
                if (lane < NW) {
                    int lo = lane * 32;
                    if (lo < M) {
                        int rem = M - lo;
                        kwq = (rem >= 32) ? 0xffffffffu : ((1u << rem) - 1u);
                    }
                }
                int nwl = (M + 31) >> 5;
                for (int w = 0; w < nwl; w++) {
                    unsigned kwv = __shfl_sync(0xffffffffu, kwq, w);  // word w, uniform
                    unsigned rw  = srow[w];
                    unsigned active = kwv & rw;
                    while (active) {                   // short chain: 1 LDS per step
                        int bb = __ffs(active) - 1;
                        unsigned row_w = smask[(w * 32 + bb) * NW + w];
                        kwv &= ~row_w;                 // mask rows hold only j>i bits
                        active = kwv & rw & (0xfffffffeu << bb);
                    }
                    if (lane == w) kwq = kwv;
                    // bulk-apply word w's surviving suppressors to later words
                    unsigned contrib = kwv & rw;
                    if (lane > w && lane < NW) {
                        unsigned acc = 0, cc = contrib;
                        while (cc) {                   // independent pipelined LDS
                            int bb = __ffs(cc) - 1; cc &= cc - 1;
                            acc |= smask[(w * 32 + bb) * NW + lane];
                        }
                        kwq &= ~acc;
                    }
                }
                if (lane < NW) skw[lane] = kwq;
            }
            __syncthreads();
            // ---- emit kept rows from precomputed row data ----
            for (int t = tid; t < M; t += NMST) {
                if ((skw[t >> 5] >> (t & 31)) & 1u) {
                    int r = sr[t];
                    int slot = c * CAP2 + t;
#pragma unroll
                    for (int q = 0; q < 6; q++) out[6 * r + q] = d_crow6[slot * 6 + q];
                }
            }
        } else {
            // ---- mid path (MMASK < M <= CAP2): pivot loop ----
            unsigned char* skbyte = (unsigned char*)smask;   // 8192B >= CAP2
            for (int t = tid; t < M; t += NMST) skbyte[t] = 1;
            __syncthreads();
            for (int i = 0; i < M - 1; i++) {
                __syncthreads();
                if (!skbyte[i]) continue;
                float4 bi = sb4[i];
                float  ai = sar[i];
                for (int j = i + 1 + tid; j < M; j += NMST) {
                    if (!skbyte[j]) continue;
                    if (sup_test4(bi, ai, sb4[j], sar[j]))
                        skbyte[j] = 0;
                }
            }
            __syncthreads();
            for (int t = tid; t < M; t += NMST) {
                if (skbyte[t]) {
                    int r = sr[t];
                    int slot = c * CAP2 + t;
#pragma unroll
                    for (int q = 0; q < 6; q++) out[6 * r + q] = d_crow6[slot * 6 + q];
                }
            }
        }
    } else {
        // ---- fallback (M > CAP2, never expected): global pivot loop via d_cand ----
        unsigned char* skbyte = (unsigned char*)sb4;     // 16KB >= 8000 >= M
        for (int t = tid; t < M; t += NMST) skbyte[t] = 1;
        __syncthreads();
        for (int i = 0; i < M - 1; i++) {
            __syncthreads();
            if (!skbyte[i]) continue;
            int oi = d_cand[c * NBOX + i] >> 16;
            float cx = d_dec6[oi * 6 + 0], cy = d_dec6[oi * 6 + 1];
            float w  = d_dec6[oi * 6 + 2], h  = d_dec6[oi * 6 + 3];
            float4 bi = make_float4(cx - 0.5f * w, cy - 0.5f * h, cx + 0.5f * w, cy + 0.5f * h);
            float ai = fabsf((bi.z - bi.x) * (bi.w - bi.y));
            for (int j = i + 1 + tid; j < M; j += NMST) {
                if (!skbyte[j]) continue;
                int oj = d_cand[c * NBOX + j] >> 16;
                float cxj = d_dec6[oj * 6 + 0], cyj = d_dec6[oj * 6 + 1];
                float wj  = d_dec6[oj * 6 + 2], hj  = d_dec6[oj * 6 + 3];
                float4 bj = make_float4(cxj - 0.5f * wj, cyj - 0.5f * hj,
                                        cxj + 0.5f * wj, cyj + 0.5f * hj);
                float aj = fabsf((bj.z - bj.x) * (bj.w - bj.y));
                if (sup_test4(bi, ai, bj, aj))
                    skbyte[j] = 0;
            }
        }
        __syncthreads();
        for (int t = tid; t < M; t += NMST) {
            if (skbyte[t]) {
                int p = d_cand[c * NBOX + t];
                int r = p & 0xffff, orig = p >> 16;
#pragma unroll
                for (int q = 0; q < 6; q++) out[6 * r + q] = d_dec6[orig * 6 + q];
            }
        }
    }
}

// ---------------- launch ----------------
extern "C" void kernel_launch(void* const* d_in, const int* in_sizes, int n_in,
                              void* d_out, int out_size) {
    const float* x;
    const float* anchors;
    if (in_sizes[0] == 10) { anchors = (const float*)d_in[0]; x = (const float*)d_in[1]; }
    else                   { x = (const float*)d_in[0]; anchors = (const float*)d_in[1]; }
    float* out = (float*)d_out;

    k_decode <<<63, 128>>>(x, anchors, out);
    k_rank   <<<IGROUPS * JC, 256>>>();
    k_nms    <<<NCLS, NMST>>>(out);
}